// round 1
// baseline (speedup 1.0000x reference)
#include <cuda_runtime.h>
#include <cstdint>
#include <cstddef>

#define BB      8192
#define IN_DIM  1024
#define H_DIM   1024
#define OUT_DIM 512

// Scratch (allocation rules forbid cudaMalloc; __device__ globals are allowed)
__device__ float g_z [BB * H_DIM];   // z gate, sigmoid applied
__device__ float g_rh[BB * H_DIM];   // r * h

__device__ __forceinline__ uint32_t f2tf32(float f) {
    uint32_t r;
    asm("cvt.rna.tf32.f32 %0, %1;" : "=r"(r) : "f"(f));
    return r;
}

__device__ __forceinline__ float sigmoidf_(float x) {
    return 1.0f / (1.0f + expf(-x));
}

// Tiled TN GEMM: C[M,N] = A[M,Ktot] @ W[N,Ktot]^T  (+ fused GRU epilogue per MODE)
// A is a virtual concat [A0 | A1] split at k=1024 for MODE 0/1/2; plain A0 for MODE 3.
// BM=BN=128, BK=32, 256 threads (8 warps as 4x2), warp tile 32x64,
// mma.sync.m16n8k8 tf32 with cvt.rna rounding.
template<int MODE>
__global__ __launch_bounds__(256)
void gru_gemm(const float* __restrict__ A0, const float* __restrict__ A1,
              const float* __restrict__ W,  const float* __restrict__ bias,
              const float* __restrict__ hprev,
              float* __restrict__ out, int Ktot, int N)
{
    __shared__ float As[128][36];   // +4 pad: conflict-free frag loads, 16B-aligned rows
    __shared__ float Ws[128][36];

    const int tid    = threadIdx.x;
    const int lane   = tid & 31;
    const int warp   = tid >> 5;
    const int warp_m = warp & 3;    // 4 m-warps * 32 rows = 128
    const int warp_n = warp >> 2;   // 2 n-warps * 64 cols = 128
    const int gid    = lane >> 2;   // 0..7
    const int tig    = lane & 3;    // 0..3

    const int blockRow = blockIdx.y * 128;
    const int blockCol = blockIdx.x * 128;

    float acc[2][8][4];
    #pragma unroll
    for (int mi = 0; mi < 2; mi++)
        #pragma unroll
        for (int ni = 0; ni < 8; ni++)
            #pragma unroll
            for (int e = 0; e < 4; e++) acc[mi][ni][e] = 0.0f;

    for (int k0 = 0; k0 < Ktot; k0 += 32) {
        // ---- stage tiles to smem ----
        const float* Asrc;
        int koff;
        if (MODE == 3)           { Asrc = A0;                         koff = k0; }
        else if (k0 < IN_DIM)    { Asrc = A0;                         koff = k0; }
        else                     { Asrc = (MODE == 2) ? g_rh : A1;    koff = k0 - IN_DIM; }

        #pragma unroll
        for (int i = 0; i < 4; i++) {
            int idx = tid + i * 256;        // 0..1023 float4 slots
            int r   = idx >> 3;             // row 0..127
            int c4  = (idx & 7) * 4;        // col 0,4,..,28
            float4 va = *(const float4*)(Asrc + (size_t)(blockRow + r) * 1024 + koff + c4);
            *(float4*)&As[r][c4] = va;
            float4 vw = *(const float4*)(W + (size_t)(blockCol + r) * Ktot + k0 + c4);
            *(float4*)&Ws[r][c4] = vw;
        }
        __syncthreads();

        // ---- 4 k-steps of m16n8k8 ----
        #pragma unroll
        for (int ks = 0; ks < 4; ks++) {
            const int k = ks * 8;
            uint32_t af[2][4];
            #pragma unroll
            for (int mi = 0; mi < 2; mi++) {
                int rb = warp_m * 32 + mi * 16;
                af[mi][0] = f2tf32(As[rb + gid    ][k + tig    ]);
                af[mi][1] = f2tf32(As[rb + gid + 8][k + tig    ]);
                af[mi][2] = f2tf32(As[rb + gid    ][k + tig + 4]);
                af[mi][3] = f2tf32(As[rb + gid + 8][k + tig + 4]);
            }
            uint32_t bf[8][2];
            #pragma unroll
            for (int ni = 0; ni < 8; ni++) {
                int cb = warp_n * 64 + ni * 8;
                bf[ni][0] = f2tf32(Ws[cb + gid][k + tig    ]);
                bf[ni][1] = f2tf32(Ws[cb + gid][k + tig + 4]);
            }
            #pragma unroll
            for (int mi = 0; mi < 2; mi++)
                #pragma unroll
                for (int ni = 0; ni < 8; ni++) {
                    asm volatile(
                        "mma.sync.aligned.m16n8k8.row.col.f32.tf32.tf32.f32 "
                        "{%0,%1,%2,%3}, {%4,%5,%6,%7}, {%8,%9}, {%0,%1,%2,%3};"
                        : "+f"(acc[mi][ni][0]), "+f"(acc[mi][ni][1]),
                          "+f"(acc[mi][ni][2]), "+f"(acc[mi][ni][3])
                        : "r"(af[mi][0]), "r"(af[mi][1]),
                          "r"(af[mi][2]), "r"(af[mi][3]),
                          "r"(bf[ni][0]), "r"(bf[ni][1]));
                }
        }
        __syncthreads();
    }

    // ---- fused epilogue ----
    #pragma unroll
    for (int mi = 0; mi < 2; mi++) {
        #pragma unroll
        for (int ni = 0; ni < 8; ni++) {
            const int row0 = blockRow + warp_m * 32 + mi * 16 + gid;
            const int col0 = blockCol + warp_n * 64 + ni * 8 + tig * 2;
            #pragma unroll
            for (int e = 0; e < 4; e++) {
                const int row = row0 + (e >> 1) * 8;
                const int col = col0 + (e & 1);
                float v = acc[mi][ni][e] + bias[col];
                if (MODE == 0) {
                    g_z[row * H_DIM + col] = sigmoidf_(v);
                } else if (MODE == 1) {
                    float r = sigmoidf_(v);
                    g_rh[row * H_DIM + col] = r * hprev[row * H_DIM + col];
                } else if (MODE == 2) {
                    float ht = tanhf(v);
                    float zz = g_z[row * H_DIM + col];
                    float hv = hprev[row * H_DIM + col];
                    out[row * H_DIM + col] = (1.0f - zz) * hv + zz * ht;
                } else {
                    out[row * N + col] = v;
                }
            }
        }
    }
}

extern "C" void kernel_launch(void* const* d_in, const int* in_sizes, int n_in,
                              void* d_out, int out_size)
{
    const float* x  = (const float*)d_in[0];
    const float* h  = (const float*)d_in[1];
    const float* Wz = (const float*)d_in[2];
    const float* bz = (const float*)d_in[3];
    const float* Wr = (const float*)d_in[4];
    const float* br = (const float*)d_in[5];
    const float* Wh = (const float*)d_in[6];
    const float* bh = (const float*)d_in[7];
    const float* Wo = (const float*)d_in[8];
    const float* bo = (const float*)d_in[9];

    float* out_o = (float*)d_out;                          // [B, OUT]
    float* out_h = (float*)d_out + (size_t)BB * OUT_DIM;   // [B, H]

    dim3 blk(256);
    dim3 g1(H_DIM / 128, BB / 128);    // (8, 64)
    dim3 g3(OUT_DIM / 128, BB / 128);  // (4, 64)

    // z = sigmoid([x|h] @ Wz^T + bz)
    gru_gemm<0><<<g1, blk>>>(x, h, Wz, bz, h, nullptr, IN_DIM + H_DIM, H_DIM);
    // rh = sigmoid([x|h] @ Wr^T + br) * h
    gru_gemm<1><<<g1, blk>>>(x, h, Wr, br, h, nullptr, IN_DIM + H_DIM, H_DIM);
    // hidden = (1-z)*h + z*tanh([x|rh] @ Wh^T + bh)
    gru_gemm<2><<<g1, blk>>>(x, nullptr, Wh, bh, h, out_h, IN_DIM + H_DIM, H_DIM);
    // output = hidden @ Wo^T + bo
    gru_gemm<3><<<g3, blk>>>(out_h, nullptr, Wo, bo, nullptr, out_o, H_DIM, OUT_DIM);
}